// round 16
// baseline (speedup 1.0000x reference)
#include <cuda_runtime.h>
#include <cuda_fp16.h>

#define NMAX    50000
#define EMAX    800000
#define FEAT    128
#define HEADS   4
#define CH      32
#define NG      64
#define NCLS    10
#define NEG     0.2f
#define NLAYERS 3

// -------- static scratch; 16B-aligned --------
__device__ __align__(16) unsigned g_xlh[NMAX * (FEAT / 2)];  // xl as packed half2 (edge-phase mirror)
__device__ __align__(16) float g_xr  [NMAX * FEAT];
__device__ __align__(16) float g_acc [NMAX * FEAT];
__device__ __align__(16) float g_pool[NG * FEAT];
__device__ __align__(16) float g_cnt [NG];
// CSR by destination
__device__ int g_cnti    [NMAX];
__device__ int g_cur     [NMAX];
__device__ int g_rowstart[NMAX + 1];
__device__ int g_col     [EMAX];
__device__ int g_bsum    [256];

// -------- helpers --------
__device__ __forceinline__ void red_add4(float* addr, float a, float b, float c, float d) {
    asm volatile("red.global.add.v4.f32 [%0], {%1, %2, %3, %4};"
                 :: "l"(addr), "f"(a), "f"(b), "f"(c), "f"(d) : "memory");
}
__device__ __forceinline__ float elu_f(float v) { return v > 0.0f ? v : expm1f(v); }

__device__ __forceinline__ float4 h2f4(uint2 v) {
    __half2 a = *(__half2*)&v.x;
    __half2 b = *(__half2*)&v.y;
    float2 lo = __half22float2(a);
    float2 hi = __half22float2(b);
    return make_float4(lo.x, lo.y, hi.x, hi.y);
}

typedef unsigned long long u64;
__device__ __forceinline__ u64 pack2(float x, float y) {
    u64 r; asm("mov.b64 %0, {%1, %2};" : "=l"(r) : "f"(x), "f"(y)); return r;
}
__device__ __forceinline__ void unpack2(u64 v, float& x, float& y) {
    asm("mov.b64 {%0, %1}, %2;" : "=f"(x), "=f"(y) : "l"(v));
}
__device__ __forceinline__ void fma2(u64& d, u64 a, u64 b) {
    asm("fma.rn.f32x2 %0, %1, %2, %0;" : "+l"(d) : "l"(a), "l"(b));
}

// ================= init + CSR build (once per launch) =================
__global__ void init_all_k(int n) {
    int i = blockIdx.x * blockDim.x + threadIdx.x;
    if (i < n) { g_cnti[i] = 0; g_cur[i] = 0; }
    if (i < NG * FEAT) g_pool[i] = 0.0f;
    if (i < NG)        g_cnt[i]  = 0.0f;
}
__global__ void csr_hist_k(const int* __restrict__ dst, int E) {
    int e = blockIdx.x * blockDim.x + threadIdx.x;
    if (e < E) atomicAdd(&g_cnti[dst[e]], 1);
}
__global__ void csr_scan1_k(int n) {
    __shared__ int sh[256];
    int tid = threadIdx.x;
    int i = blockIdx.x * 256 + tid;
    int v = (i < n) ? g_cnti[i] : 0;
    sh[tid] = v;
    __syncthreads();
    #pragma unroll
    for (int off = 1; off < 256; off <<= 1) {
        int t = (tid >= off) ? sh[tid - off] : 0;
        __syncthreads();
        sh[tid] += t;
        __syncthreads();
    }
    if (i < n) g_rowstart[i] = sh[tid] - v;
    if (tid == 255) g_bsum[blockIdx.x] = sh[255];
}
__global__ void csr_scan2_k(int nb, int n) {
    __shared__ int sh[256];
    int tid = threadIdx.x;
    int v = (tid < nb) ? g_bsum[tid] : 0;
    sh[tid] = v;
    __syncthreads();
    #pragma unroll
    for (int off = 1; off < 256; off <<= 1) {
        int t = (tid >= off) ? sh[tid - off] : 0;
        __syncthreads();
        sh[tid] += t;
        __syncthreads();
    }
    if (tid < nb) g_bsum[tid] = sh[tid] - v;
    if (tid == 255) g_rowstart[n] = sh[255];
}
__global__ void csr_scan3_k(int n) {
    int i = blockIdx.x * 256 + threadIdx.x;
    if (i < n) g_rowstart[i] += g_bsum[blockIdx.x];
}
__global__ void csr_scatter_k(const int* __restrict__ src, const int* __restrict__ dst, int E) {
    int e = blockIdx.x * blockDim.x + threadIdx.x;
    if (e >= E) return;
    int d = dst[e];
    int p = atomicAdd(&g_cur[d], 1);
    g_col[g_rowstart[d] + p] = src[e];
}

// ================= fused GEMM: xl(half) = act@Wl+bl, xr = act@Wr+br =================
__global__ void gemm_lr_k(const float* __restrict__ x_in, int layer,
                          const float* __restrict__ Wl, const float* __restrict__ Wr,
                          const float* __restrict__ bl, const float* __restrict__ br,
                          int n) {
    __shared__ __align__(16) u64 xs2[32][FEAT + 2];   // (v,v) pairs
    int tid  = threadIdx.x;
    int base = blockIdx.x * 32;

    #pragma unroll
    for (int j = 0; j < 8; j++) {
        int idx4 = tid + j * 128;
        int r = idx4 >> 5, c4l = (idx4 & 31) * 4;
        int node = base + r;
        float4 v = make_float4(0.f, 0.f, 0.f, 0.f);
        if (node < n) {
            if (layer == 0) {
                v = *(const float4*)&x_in[node * FEAT + c4l];
            } else {
                v = *(const float4*)&g_acc[node * FEAT + c4l];
                v.x = elu_f(v.x); v.y = elu_f(v.y); v.z = elu_f(v.z); v.w = elu_f(v.w);
            }
        }
        ulonglong2 p0, p1;
        p0.x = pack2(v.x, v.x); p0.y = pack2(v.y, v.y);
        p1.x = pack2(v.z, v.z); p1.y = pack2(v.w, v.w);
        *(ulonglong2*)&xs2[r][c4l]     = p0;
        *(ulonglong2*)&xs2[r][c4l + 2] = p1;
    }
    __syncthreads();

    int cp = tid & 31;
    int rh = tid >> 5;

    const ulonglong2* Wl4 = (const ulonglong2*)Wl;
    const ulonglong2* Wr4 = (const ulonglong2*)Wr;

    u64 aL0[8], aL1[8], aR0[8], aR1[8];
    #pragma unroll
    for (int i = 0; i < 8; i++) { aL0[i]=0ull; aL1[i]=0ull; aR0[i]=0ull; aR1[i]=0ull; }

    #pragma unroll 4
    for (int k = 0; k < FEAT; k++) {
        ulonglong2 wl = Wl4[k * 32 + cp];
        ulonglong2 wr = Wr4[k * 32 + cp];
        #pragma unroll
        for (int i = 0; i < 8; i++) {
            u64 xv2 = xs2[rh * 8 + i][k];
            fma2(aL0[i], xv2, wl.x);
            fma2(aL1[i], xv2, wl.y);
            fma2(aR0[i], xv2, wr.x);
            fma2(aR1[i], xv2, wr.y);
        }
    }

    int c4 = cp * 4;
    float4 bL = *(const float4*)&bl[c4];
    float4 bR = *(const float4*)&br[c4];
    #pragma unroll
    for (int i = 0; i < 8; i++) {
        int node = base + rh * 8 + i;
        if (node < n) {
            float4 o;
            unpack2(aL0[i], o.x, o.y); unpack2(aL1[i], o.z, o.w);
            o.x += bL.x; o.y += bL.y; o.z += bL.z; o.w += bL.w;
            // xl stored ONLY as packed half2 (edge phase consumes fp16)
            __half2 h01 = __floats2half2_rn(o.x, o.y);
            __half2 h23 = __floats2half2_rn(o.z, o.w);
            uint2 hv;
            hv.x = *(unsigned*)&h01;
            hv.y = *(unsigned*)&h23;
            *(uint2*)&g_xlh[(size_t)node * (FEAT / 2) + cp * 2] = hv;
            unpack2(aR0[i], o.x, o.y); unpack2(aR1[i], o.z, o.w);
            o.x += bR.x; o.y += bR.y; o.z += bR.z; o.w += bR.w;
            *(float4*)&g_xr[(size_t)node * FEAT + c4] = o;
        }
    }
}

// ================= fused edge pass: warp per destination node =================
#define SCORE4(x4, q)  do { \
    float _z; \
    _z = (x4).x + xr4.x; q = fmaf(fmaxf(_z, NEG * _z), a.x, q); \
    _z = (x4).y + xr4.y; q = fmaf(fmaxf(_z, NEG * _z), a.y, q); \
    _z = (x4).z + xr4.z; q = fmaf(fmaxf(_z, NEG * _z), a.z, q); \
    _z = (x4).w + xr4.w; q = fmaf(fmaxf(_z, NEG * _z), a.w, q); \
} while (0)

template <int POOL>
__global__ void dst_pass_k(const float* __restrict__ att,
                           const float* __restrict__ bias,
                           const int* __restrict__ batch, int n) {
    int d    = (blockIdx.x * blockDim.x + threadIdx.x) >> 5;
    int lane = threadIdx.x & 31;
    if (d >= n) return;
    int c4 = lane * 4;
    int h2 = lane * 2;          // half2 index for this lane's 4 channels

    float4 a   = *(const float4*)&att [c4];
    float4 xr4 = *(const float4*)&g_xr[(size_t)d * FEAT + c4];
    float4 xld = h2f4(*(const uint2*)&g_xlh[(size_t)d * (FEAT / 2) + h2]);

    float p = 0.0f;
    SCORE4(xld, p);
    p += __shfl_xor_sync(0xffffffffu, p, 1);
    p += __shfl_xor_sync(0xffffffffu, p, 2);
    p += __shfl_xor_sync(0xffffffffu, p, 4);
    float w = __expf(p);
    float4 acc0 = make_float4(w * xld.x, w * xld.y, w * xld.z, w * xld.w);
    float4 acc1 = make_float4(0.f, 0.f, 0.f, 0.f);
    float4 acc2 = make_float4(0.f, 0.f, 0.f, 0.f);
    float4 acc3 = make_float4(0.f, 0.f, 0.f, 0.f);
    float den0 = w, den1 = 0.f, den2 = 0.f, den3 = 0.f;

    int beg = g_rowstart[d], end = g_rowstart[d + 1];
    for (int j0 = beg; j0 < end; j0 += 32) {
        int sv = (j0 + lane < end) ? g_col[j0 + lane] : 0;
        int cnt = min(32, end - j0);
        int k = 0;
        for (; k + 3 < cnt; k += 4) {
            int s0 = __shfl_sync(0xffffffffu, sv, k);
            int s1 = __shfl_sync(0xffffffffu, sv, k + 1);
            int s2 = __shfl_sync(0xffffffffu, sv, k + 2);
            int s3 = __shfl_sync(0xffffffffu, sv, k + 3);
            uint2 v0 = *(const uint2*)&g_xlh[(size_t)s0 * (FEAT / 2) + h2];
            uint2 v1 = *(const uint2*)&g_xlh[(size_t)s1 * (FEAT / 2) + h2];
            uint2 v2 = *(const uint2*)&g_xlh[(size_t)s2 * (FEAT / 2) + h2];
            uint2 v3 = *(const uint2*)&g_xlh[(size_t)s3 * (FEAT / 2) + h2];
            float4 x0 = h2f4(v0);
            float4 x1 = h2f4(v1);
            float4 x2 = h2f4(v2);
            float4 x3 = h2f4(v3);
            float q0 = 0.f, q1 = 0.f, q2 = 0.f, q3 = 0.f;
            SCORE4(x0, q0); SCORE4(x1, q1); SCORE4(x2, q2); SCORE4(x3, q3);
            q0 += __shfl_xor_sync(0xffffffffu, q0, 1);
            q1 += __shfl_xor_sync(0xffffffffu, q1, 1);
            q2 += __shfl_xor_sync(0xffffffffu, q2, 1);
            q3 += __shfl_xor_sync(0xffffffffu, q3, 1);
            q0 += __shfl_xor_sync(0xffffffffu, q0, 2);
            q1 += __shfl_xor_sync(0xffffffffu, q1, 2);
            q2 += __shfl_xor_sync(0xffffffffu, q2, 2);
            q3 += __shfl_xor_sync(0xffffffffu, q3, 2);
            q0 += __shfl_xor_sync(0xffffffffu, q0, 4);
            q1 += __shfl_xor_sync(0xffffffffu, q1, 4);
            q2 += __shfl_xor_sync(0xffffffffu, q2, 4);
            q3 += __shfl_xor_sync(0xffffffffu, q3, 4);
            float w0 = __expf(q0), w1 = __expf(q1), w2 = __expf(q2), w3 = __expf(q3);
            acc0.x = fmaf(w0, x0.x, acc0.x); acc1.x = fmaf(w1, x1.x, acc1.x);
            acc2.x = fmaf(w2, x2.x, acc2.x); acc3.x = fmaf(w3, x3.x, acc3.x);
            acc0.y = fmaf(w0, x0.y, acc0.y); acc1.y = fmaf(w1, x1.y, acc1.y);
            acc2.y = fmaf(w2, x2.y, acc2.y); acc3.y = fmaf(w3, x3.y, acc3.y);
            acc0.z = fmaf(w0, x0.z, acc0.z); acc1.z = fmaf(w1, x1.z, acc1.z);
            acc2.z = fmaf(w2, x2.z, acc2.z); acc3.z = fmaf(w3, x3.z, acc3.z);
            acc0.w = fmaf(w0, x0.w, acc0.w); acc1.w = fmaf(w1, x1.w, acc1.w);
            acc2.w = fmaf(w2, x2.w, acc2.w); acc3.w = fmaf(w3, x3.w, acc3.w);
            den0 += w0; den1 += w1; den2 += w2; den3 += w3;
        }
        for (; k < cnt; k++) {
            int s0 = __shfl_sync(0xffffffffu, sv, k);
            float4 x0 = h2f4(*(const uint2*)&g_xlh[(size_t)s0 * (FEAT / 2) + h2]);
            float q0 = 0.f;
            SCORE4(x0, q0);
            q0 += __shfl_xor_sync(0xffffffffu, q0, 1);
            q0 += __shfl_xor_sync(0xffffffffu, q0, 2);
            q0 += __shfl_xor_sync(0xffffffffu, q0, 4);
            float w0 = __expf(q0);
            acc0.x = fmaf(w0, x0.x, acc0.x);
            acc0.y = fmaf(w0, x0.y, acc0.y);
            acc0.z = fmaf(w0, x0.z, acc0.z);
            acc0.w = fmaf(w0, x0.w, acc0.w);
            den0 += w0;
        }
    }

    float inv = 1.0f / ((den0 + den1) + (den2 + den3));
    float4 b4 = *(const float4*)&bias[c4];
    float4 o;
    o.x = fmaf((acc0.x + acc1.x) + (acc2.x + acc3.x), inv, b4.x);
    o.y = fmaf((acc0.y + acc1.y) + (acc2.y + acc3.y), inv, b4.y);
    o.z = fmaf((acc0.z + acc1.z) + (acc2.z + acc3.z), inv, b4.z);
    o.w = fmaf((acc0.w + acc1.w) + (acc2.w + acc3.w), inv, b4.w);

    if (POOL) {
        o.x = elu_f(o.x); o.y = elu_f(o.y); o.z = elu_f(o.z); o.w = elu_f(o.w);
        int b = batch[d];
        red_add4(&g_pool[b * FEAT + c4], o.x, o.y, o.z, o.w);
        if (lane == 0) atomicAdd(&g_cnt[b], 1.0f);
    } else {
        *(float4*)&g_acc[(size_t)d * FEAT + c4] = o;
    }
}

// ================= classifier =================
__global__ void head_k(const float* __restrict__ lin_w, const float* __restrict__ lin_b,
                       float* __restrict__ out) {
    int g = blockIdx.x;
    int k = threadIdx.x;
    __shared__ float lg[NCLS];
    float inv = 1.0f / fmaxf(g_cnt[g], 1.0f);
    if (k < NCLS) {
        float acc = lin_b[k];
        for (int c = 0; c < FEAT; c++)
            acc = fmaf(g_pool[g * FEAT + c] * inv, lin_w[c * NCLS + k], acc);
        lg[k] = elu_f(acc);
    }
    __syncthreads();
    if (k < NCLS) {
        float m = lg[0];
        #pragma unroll
        for (int j = 1; j < NCLS; j++) m = fmaxf(m, lg[j]);
        float ssum = 0.0f;
        #pragma unroll
        for (int j = 0; j < NCLS; j++) ssum += expf(lg[j] - m);
        out[g * NCLS + k] = lg[k] - m - logf(ssum);
    }
}

// ================= launch =================
extern "C" void kernel_launch(void* const* d_in, const int* in_sizes, int n_in,
                              void* d_out, int out_size) {
    const float* x     = (const float*)d_in[0];
    const int*   ei    = (const int*)d_in[1];
    const int*   batch = (const int*)d_in[2];
    const float* Wl    = (const float*)d_in[3];
    const float* Wr    = (const float*)d_in[4];
    const float* bl    = (const float*)d_in[5];
    const float* br    = (const float*)d_in[6];
    const float* att   = (const float*)d_in[7];
    const float* bias  = (const float*)d_in[8];
    const float* lin_w = (const float*)d_in[9];
    const float* lin_b = (const float*)d_in[10];
    float*       out   = (float*)d_out;

    int E = in_sizes[1] / 2;
    int n = in_sizes[0] / FEAT;

    const int* src = ei;
    const int* dst = ei + E;

    const int T = 256;
    int g_n    = (n + T - 1) / T;
    int g_e    = (E + T - 1) / T;
    int g_gemm = (n + 31) / 32;
    int g_dstW = (int)(((long long)n * 32 + T - 1) / T);
    int nb     = (n + 255) / 256;

    init_all_k<<<g_n, T>>>(n);
    csr_hist_k<<<g_e, T>>>(dst, E);
    csr_scan1_k<<<nb, 256>>>(n);
    csr_scan2_k<<<1, 256>>>(nb, n);
    csr_scan3_k<<<nb, 256>>>(n);
    csr_scatter_k<<<g_e, T>>>(src, dst, E);

    for (int l = 0; l < NLAYERS; l++) {
        gemm_lr_k<<<g_gemm, 128>>>(x, l,
                                   Wl + l * FEAT * FEAT, Wr + l * FEAT * FEAT,
                                   bl + l * FEAT, br + l * FEAT, n);
        if (l < NLAYERS - 1)
            dst_pass_k<0><<<g_dstW, T>>>(att + l * HEADS * CH, bias + l * FEAT, batch, n);
        else
            dst_pass_k<1><<<g_dstW, T>>>(att + l * HEADS * CH, bias + l * FEAT, batch, n);
    }

    head_k<<<NG, 32>>>(lin_w, lin_b, out);
}

// round 17
// speedup vs baseline: 1.5777x; 1.5777x over previous
#include <cuda_runtime.h>

#define NMAX    50000
#define EMAX    800000
#define FEAT    128
#define HEADS   4
#define CH      32
#define NG      64
#define NCLS    10
#define NEG     0.2f
#define NLAYERS 3

// -------- static scratch; 16B-aligned --------
__device__ __align__(16) float g_xl  [NMAX * FEAT];
__device__ __align__(16) float g_xr  [NMAX * FEAT];
__device__ __align__(16) float g_acc [NMAX * FEAT];
__device__ __align__(16) float g_pool[NG * FEAT];
__device__ __align__(16) float g_cnt [NG];
// CSR by destination
__device__ int g_cnti    [NMAX];
__device__ int g_cur     [NMAX];
__device__ int g_rowstart[NMAX + 1];
__device__ int g_col     [EMAX];
__device__ int g_bsum    [256];

// -------- helpers --------
__device__ __forceinline__ void red_add4(float* addr, float a, float b, float c, float d) {
    asm volatile("red.global.add.v4.f32 [%0], {%1, %2, %3, %4};"
                 :: "l"(addr), "f"(a), "f"(b), "f"(c), "f"(d) : "memory");
}
__device__ __forceinline__ float elu_f(float v) { return v > 0.0f ? v : expm1f(v); }

typedef unsigned long long u64;
__device__ __forceinline__ u64 pack2(float x, float y) {
    u64 r; asm("mov.b64 %0, {%1, %2};" : "=l"(r) : "f"(x), "f"(y)); return r;
}
__device__ __forceinline__ void unpack2(u64 v, float& x, float& y) {
    asm("mov.b64 {%0, %1}, %2;" : "=f"(x), "=f"(y) : "l"(v));
}
__device__ __forceinline__ void fma2(u64& d, u64 a, u64 b) {
    asm("fma.rn.f32x2 %0, %1, %2, %0;" : "+l"(d) : "l"(a), "l"(b));
}

// ================= init + CSR build (once per launch; side stream) =================
__global__ void init_all_k(int n) {
    int i = blockIdx.x * blockDim.x + threadIdx.x;
    if (i < n) { g_cnti[i] = 0; g_cur[i] = 0; }
    if (i < NG * FEAT) g_pool[i] = 0.0f;
    if (i < NG)        g_cnt[i]  = 0.0f;
}
__global__ void csr_hist_k(const int* __restrict__ dst, int E) {
    int e = blockIdx.x * blockDim.x + threadIdx.x;
    if (e < E) atomicAdd(&g_cnti[dst[e]], 1);
}
__global__ void csr_scan1_k(int n) {
    __shared__ int sh[256];
    int tid = threadIdx.x;
    int i = blockIdx.x * 256 + tid;
    int v = (i < n) ? g_cnti[i] : 0;
    sh[tid] = v;
    __syncthreads();
    #pragma unroll
    for (int off = 1; off < 256; off <<= 1) {
        int t = (tid >= off) ? sh[tid - off] : 0;
        __syncthreads();
        sh[tid] += t;
        __syncthreads();
    }
    if (i < n) g_rowstart[i] = sh[tid] - v;
    if (tid == 255) g_bsum[blockIdx.x] = sh[255];
}
__global__ void csr_scan2_k(int nb, int n) {
    __shared__ int sh[256];
    int tid = threadIdx.x;
    int v = (tid < nb) ? g_bsum[tid] : 0;
    sh[tid] = v;
    __syncthreads();
    #pragma unroll
    for (int off = 1; off < 256; off <<= 1) {
        int t = (tid >= off) ? sh[tid - off] : 0;
        __syncthreads();
        sh[tid] += t;
        __syncthreads();
    }
    if (tid < nb) g_bsum[tid] = sh[tid] - v;
    if (tid == 255) g_rowstart[n] = sh[255];
}
__global__ void csr_scan3_k(int n) {
    int i = blockIdx.x * 256 + threadIdx.x;
    if (i < n) g_rowstart[i] += g_bsum[blockIdx.x];
}
__global__ void csr_scatter_k(const int* __restrict__ src, const int* __restrict__ dst, int E) {
    int e = blockIdx.x * blockDim.x + threadIdx.x;
    if (e >= E) return;
    int d = dst[e];
    int p = atomicAdd(&g_cur[d], 1);
    g_col[g_rowstart[d] + p] = src[e];
}

// ================= fused GEMM: xl = act@Wl+bl, xr = act@Wr+br (R15) =================
__global__ void gemm_lr_k(const float* __restrict__ x_in, int layer,
                          const float* __restrict__ Wl, const float* __restrict__ Wr,
                          const float* __restrict__ bl, const float* __restrict__ br,
                          int n) {
    __shared__ __align__(16) u64 xs2[32][FEAT + 2];   // (v,v) pairs, 33 KB
    int tid  = threadIdx.x;
    int base = blockIdx.x * 32;

    #pragma unroll
    for (int j = 0; j < 8; j++) {
        int idx4 = tid + j * 128;
        int r = idx4 >> 5, c4l = (idx4 & 31) * 4;
        int node = base + r;
        float4 v = make_float4(0.f, 0.f, 0.f, 0.f);
        if (node < n) {
            if (layer == 0) {
                v = *(const float4*)&x_in[node * FEAT + c4l];
            } else {
                v = *(const float4*)&g_acc[node * FEAT + c4l];
                v.x = elu_f(v.x); v.y = elu_f(v.y); v.z = elu_f(v.z); v.w = elu_f(v.w);
            }
        }
        ulonglong2 p0, p1;
        p0.x = pack2(v.x, v.x); p0.y = pack2(v.y, v.y);
        p1.x = pack2(v.z, v.z); p1.y = pack2(v.w, v.w);
        *(ulonglong2*)&xs2[r][c4l]     = p0;
        *(ulonglong2*)&xs2[r][c4l + 2] = p1;
    }
    __syncthreads();

    int cp = tid & 31;
    int rh = tid >> 5;

    const ulonglong2* Wl4 = (const ulonglong2*)Wl;
    const ulonglong2* Wr4 = (const ulonglong2*)Wr;

    u64 aL0[8], aL1[8], aR0[8], aR1[8];
    #pragma unroll
    for (int i = 0; i < 8; i++) { aL0[i]=0ull; aL1[i]=0ull; aR0[i]=0ull; aR1[i]=0ull; }

    #pragma unroll 4
    for (int k = 0; k < FEAT; k++) {
        ulonglong2 wl = Wl4[k * 32 + cp];
        ulonglong2 wr = Wr4[k * 32 + cp];
        #pragma unroll
        for (int i = 0; i < 8; i++) {
            u64 xv2 = xs2[rh * 8 + i][k];     // LDS.64 broadcast, pre-duplicated
            fma2(aL0[i], xv2, wl.x);
            fma2(aL1[i], xv2, wl.y);
            fma2(aR0[i], xv2, wr.x);
            fma2(aR1[i], xv2, wr.y);
        }
    }

    int c4 = cp * 4;
    float4 bL = *(const float4*)&bl[c4];
    float4 bR = *(const float4*)&br[c4];
    #pragma unroll
    for (int i = 0; i < 8; i++) {
        int node = base + rh * 8 + i;
        if (node < n) {
            float4 o;
            unpack2(aL0[i], o.x, o.y); unpack2(aL1[i], o.z, o.w);
            o.x += bL.x; o.y += bL.y; o.z += bL.z; o.w += bL.w;
            *(float4*)&g_xl[(size_t)node * FEAT + c4] = o;
            unpack2(aR0[i], o.x, o.y); unpack2(aR1[i], o.z, o.w);
            o.x += bR.x; o.y += bR.y; o.z += bR.z; o.w += bR.w;
            *(float4*)&g_xr[(size_t)node * FEAT + c4] = o;
        }
    }
}

// ================= fused edge pass: warp per destination node (R11/R15) =================
#define SCORE4(x4, q)  do { \
    float _z; \
    _z = (x4).x + xr4.x; q = fmaf(fmaxf(_z, NEG * _z), a.x, q); \
    _z = (x4).y + xr4.y; q = fmaf(fmaxf(_z, NEG * _z), a.y, q); \
    _z = (x4).z + xr4.z; q = fmaf(fmaxf(_z, NEG * _z), a.z, q); \
    _z = (x4).w + xr4.w; q = fmaf(fmaxf(_z, NEG * _z), a.w, q); \
} while (0)

template <int POOL>
__global__ void dst_pass_k(const float* __restrict__ att,
                           const float* __restrict__ bias,
                           const int* __restrict__ batch, int n) {
    int d    = (blockIdx.x * blockDim.x + threadIdx.x) >> 5;
    int lane = threadIdx.x & 31;
    if (d >= n) return;
    int c4 = lane * 4;

    float4 a   = *(const float4*)&att [c4];
    float4 xr4 = *(const float4*)&g_xr[(size_t)d * FEAT + c4];
    float4 xld = *(const float4*)&g_xl[(size_t)d * FEAT + c4];

    float p = 0.0f;
    SCORE4(xld, p);
    p += __shfl_xor_sync(0xffffffffu, p, 1);
    p += __shfl_xor_sync(0xffffffffu, p, 2);
    p += __shfl_xor_sync(0xffffffffu, p, 4);
    float w = __expf(p);
    float4 acc0 = make_float4(w * xld.x, w * xld.y, w * xld.z, w * xld.w);
    float4 acc1 = make_float4(0.f, 0.f, 0.f, 0.f);
    float4 acc2 = make_float4(0.f, 0.f, 0.f, 0.f);
    float4 acc3 = make_float4(0.f, 0.f, 0.f, 0.f);
    float den0 = w, den1 = 0.f, den2 = 0.f, den3 = 0.f;

    int beg = g_rowstart[d], end = g_rowstart[d + 1];
    for (int j0 = beg; j0 < end; j0 += 32) {
        int sv = (j0 + lane < end) ? g_col[j0 + lane] : 0;
        int cnt = min(32, end - j0);
        int k = 0;
        for (; k + 3 < cnt; k += 4) {
            int s0 = __shfl_sync(0xffffffffu, sv, k);
            int s1 = __shfl_sync(0xffffffffu, sv, k + 1);
            int s2 = __shfl_sync(0xffffffffu, sv, k + 2);
            int s3 = __shfl_sync(0xffffffffu, sv, k + 3);
            float4 x0 = *(const float4*)&g_xl[(size_t)s0 * FEAT + c4];
            float4 x1 = *(const float4*)&g_xl[(size_t)s1 * FEAT + c4];
            float4 x2 = *(const float4*)&g_xl[(size_t)s2 * FEAT + c4];
            float4 x3 = *(const float4*)&g_xl[(size_t)s3 * FEAT + c4];
            float q0 = 0.f, q1 = 0.f, q2 = 0.f, q3 = 0.f;
            SCORE4(x0, q0); SCORE4(x1, q1); SCORE4(x2, q2); SCORE4(x3, q3);
            q0 += __shfl_xor_sync(0xffffffffu, q0, 1);
            q1 += __shfl_xor_sync(0xffffffffu, q1, 1);
            q2 += __shfl_xor_sync(0xffffffffu, q2, 1);
            q3 += __shfl_xor_sync(0xffffffffu, q3, 1);
            q0 += __shfl_xor_sync(0xffffffffu, q0, 2);
            q1 += __shfl_xor_sync(0xffffffffu, q1, 2);
            q2 += __shfl_xor_sync(0xffffffffu, q2, 2);
            q3 += __shfl_xor_sync(0xffffffffu, q3, 2);
            q0 += __shfl_xor_sync(0xffffffffu, q0, 4);
            q1 += __shfl_xor_sync(0xffffffffu, q1, 4);
            q2 += __shfl_xor_sync(0xffffffffu, q2, 4);
            q3 += __shfl_xor_sync(0xffffffffu, q3, 4);
            float w0 = __expf(q0), w1 = __expf(q1), w2 = __expf(q2), w3 = __expf(q3);
            acc0.x = fmaf(w0, x0.x, acc0.x); acc1.x = fmaf(w1, x1.x, acc1.x);
            acc2.x = fmaf(w2, x2.x, acc2.x); acc3.x = fmaf(w3, x3.x, acc3.x);
            acc0.y = fmaf(w0, x0.y, acc0.y); acc1.y = fmaf(w1, x1.y, acc1.y);
            acc2.y = fmaf(w2, x2.y, acc2.y); acc3.y = fmaf(w3, x3.y, acc3.y);
            acc0.z = fmaf(w0, x0.z, acc0.z); acc1.z = fmaf(w1, x1.z, acc1.z);
            acc2.z = fmaf(w2, x2.z, acc2.z); acc3.z = fmaf(w3, x3.z, acc3.z);
            acc0.w = fmaf(w0, x0.w, acc0.w); acc1.w = fmaf(w1, x1.w, acc1.w);
            acc2.w = fmaf(w2, x2.w, acc2.w); acc3.w = fmaf(w3, x3.w, acc3.w);
            den0 += w0; den1 += w1; den2 += w2; den3 += w3;
        }
        for (; k < cnt; k++) {
            int s0 = __shfl_sync(0xffffffffu, sv, k);
            float4 x0 = *(const float4*)&g_xl[(size_t)s0 * FEAT + c4];
            float q0 = 0.f;
            SCORE4(x0, q0);
            q0 += __shfl_xor_sync(0xffffffffu, q0, 1);
            q0 += __shfl_xor_sync(0xffffffffu, q0, 2);
            q0 += __shfl_xor_sync(0xffffffffu, q0, 4);
            float w0 = __expf(q0);
            acc0.x = fmaf(w0, x0.x, acc0.x);
            acc0.y = fmaf(w0, x0.y, acc0.y);
            acc0.z = fmaf(w0, x0.z, acc0.z);
            acc0.w = fmaf(w0, x0.w, acc0.w);
            den0 += w0;
        }
    }

    float inv = 1.0f / ((den0 + den1) + (den2 + den3));
    float4 b4 = *(const float4*)&bias[c4];
    float4 o;
    o.x = fmaf((acc0.x + acc1.x) + (acc2.x + acc3.x), inv, b4.x);
    o.y = fmaf((acc0.y + acc1.y) + (acc2.y + acc3.y), inv, b4.y);
    o.z = fmaf((acc0.z + acc1.z) + (acc2.z + acc3.z), inv, b4.z);
    o.w = fmaf((acc0.w + acc1.w) + (acc2.w + acc3.w), inv, b4.w);

    if (POOL) {
        o.x = elu_f(o.x); o.y = elu_f(o.y); o.z = elu_f(o.z); o.w = elu_f(o.w);
        int b = batch[d];
        red_add4(&g_pool[b * FEAT + c4], o.x, o.y, o.z, o.w);
        if (lane == 0) atomicAdd(&g_cnt[b], 1.0f);
    } else {
        *(float4*)&g_acc[(size_t)d * FEAT + c4] = o;
    }
}

// ================= classifier =================
__global__ void head_k(const float* __restrict__ lin_w, const float* __restrict__ lin_b,
                       float* __restrict__ out) {
    int g = blockIdx.x;
    int k = threadIdx.x;
    __shared__ float lg[NCLS];
    float inv = 1.0f / fmaxf(g_cnt[g], 1.0f);
    if (k < NCLS) {
        float acc = lin_b[k];
        for (int c = 0; c < FEAT; c++)
            acc = fmaf(g_pool[g * FEAT + c] * inv, lin_w[c * NCLS + k], acc);
        lg[k] = elu_f(acc);
    }
    __syncthreads();
    if (k < NCLS) {
        float m = lg[0];
        #pragma unroll
        for (int j = 1; j < NCLS; j++) m = fmaxf(m, lg[j]);
        float ssum = 0.0f;
        #pragma unroll
        for (int j = 0; j < NCLS; j++) ssum += expf(lg[j] - m);
        out[g * NCLS + k] = lg[k] - m - logf(ssum);
    }
}

// ================= launch =================
extern "C" void kernel_launch(void* const* d_in, const int* in_sizes, int n_in,
                              void* d_out, int out_size) {
    const float* x     = (const float*)d_in[0];
    const int*   ei    = (const int*)d_in[1];
    const int*   batch = (const int*)d_in[2];
    const float* Wl    = (const float*)d_in[3];
    const float* Wr    = (const float*)d_in[4];
    const float* bl    = (const float*)d_in[5];
    const float* br    = (const float*)d_in[6];
    const float* att   = (const float*)d_in[7];
    const float* bias  = (const float*)d_in[8];
    const float* lin_w = (const float*)d_in[9];
    const float* lin_b = (const float*)d_in[10];
    float*       out   = (float*)d_out;

    int E = in_sizes[1] / 2;
    int n = in_sizes[0] / FEAT;

    const int* src = ei;
    const int* dst = ei + E;

    // one-time stream/event setup (first call is the uncaptured correctness run;
    // creates no device-heap memory and changes no launched work)
    static cudaStream_t s2 = nullptr;
    static cudaEvent_t  evA = nullptr, evB = nullptr;
    if (s2 == nullptr) {
        cudaStreamCreateWithFlags(&s2, cudaStreamNonBlocking);
        cudaEventCreateWithFlags(&evA, cudaEventDisableTiming);
        cudaEventCreateWithFlags(&evB, cudaEventDisableTiming);
    }

    const int T = 256;
    int g_n    = (n + T - 1) / T;
    int g_e    = (E + T - 1) / T;
    int g_gemm = (n + 31) / 32;
    int g_dstW = (int)(((long long)n * 32 + T - 1) / T);
    int nb     = (n + 255) / 256;

    // fork: CSR build on side stream, overlapped with layer-0 GEMM
    cudaEventRecord(evA, 0);
    cudaStreamWaitEvent(s2, evA, 0);
    init_all_k  <<<g_n, T, 0, s2>>>(n);
    csr_hist_k  <<<g_e, T, 0, s2>>>(dst, E);
    csr_scan1_k <<<nb, 256, 0, s2>>>(n);
    csr_scan2_k <<<1, 256, 0, s2>>>(nb, n);
    csr_scan3_k <<<nb, 256, 0, s2>>>(n);
    csr_scatter_k<<<g_e, T, 0, s2>>>(src, dst, E);
    cudaEventRecord(evB, s2);

    // main stream: layer-0 GEMM runs concurrently with CSR build
    gemm_lr_k<<<g_gemm, 128>>>(x, 0, Wl, Wr, bl, br, n);
    cudaStreamWaitEvent(0, evB, 0);   // join before first edge pass

    for (int l = 0; l < NLAYERS; l++) {
        if (l > 0)
            gemm_lr_k<<<g_gemm, 128>>>(x, l,
                                       Wl + l * FEAT * FEAT, Wr + l * FEAT * FEAT,
                                       bl + l * FEAT, br + l * FEAT, n);
        if (l < NLAYERS - 1)
            dst_pass_k<0><<<g_dstW, T>>>(att + l * HEADS * CH, bias + l * FEAT, batch, n);
        else
            dst_pass_k<1><<<g_dstW, T>>>(att + l * HEADS * CH, bias + l * FEAT, batch, n);
    }

    head_k<<<NG, 32>>>(lin_w, lin_b, out);
}